// round 14
// baseline (speedup 1.0000x reference)
#include <cuda_runtime.h>
#include <cuda_bf16.h>
#include <cstdint>

// ---------------------------------------------------------------------------
// BiRNN (bidirectional masked LSTM), B=64, S=1024, D=U=512.
// Split design:
//   1) birnn_xconv : x -> bf16 limb fragments (mma register layout) in g_xA
//   2) birnn_xgemm : zx = x @ Wx for ALL timesteps (bulk GEMM, 1024 blocks)
//   3) birnn_loop  : sequential recurrence, h-half GEMM only (K=512),
//                    warp-autonomous: A frags via direct LDG.cg from g_hA,
//                    fine-grained per-group flags instead of a grid barrier.
// mma.sync m16n8k16 bf16 with limb-split (3 products) -> fp32-grade accuracy.
// ---------------------------------------------------------------------------

namespace {
constexpr int Bk = 64;
constexpr int Sk = 1024;
constexpr int Dk = 512;
constexpr int Uk = 512;
constexpr int THREADS  = 256;          // 8 warps: wr = wid&3 (M16), nh = wid>>2 (N16)
constexpr int NBLK_DIR = 64;
constexpr uint32_t SUB_B   = 16384;    // 16KB sub-chunk = 4 k16-steps
constexpr uint32_t CHUNK32 = 32768;    // xconv 32KB chunk granularity
constexpr uint32_t XSTEP_B = 131072;   // x fragments per timestep (32 ks)

// xgemm smem layout (bytes)
constexpr uint32_t XG_W    = 0;        // W-x frags: 32ks x2limb x2nh x32 x16B = 64KB
constexpr uint32_t XG_A    = 65536;    // ring: 4 x 16KB
constexpr uint32_t XG_SMEM = 131072;

// loop smem layout (bytes) — no A ring anymore
constexpr uint32_t LP_W    = 0;        // W-h frags: 64KB
constexpr uint32_t LP_ZX   = 65536;    // zx tile [64][40] f32 = 10240
constexpr uint32_t LP_Z    = 75776;    // zS [64][34] f32 = 8704
constexpr uint32_t LP_H    = 84480;    // sH [64][9] f32 = 2304
constexpr uint32_t LP_C    = 86784;    // sC [64][9] f32 = 2304
constexpr uint32_t LP_BI   = 89088;    // bias [32] f32
constexpr uint32_t LP_LEN  = 89216;    // lengths [64] int
constexpr uint32_t LP_SMEM = 89472;
}

// persistent device state
__device__ __align__(16) unsigned char g_xA[(size_t)Sk * XSTEP_B];   // 128 MB
__device__ __align__(16) unsigned char g_hA[2][2][XSTEP_B];          // 512 KB
__device__ float    g_zx[2][NBLK_DIR][Sk][Bk * 32];                  // 1 GB
__device__ int      g_len[Bk];
__device__ unsigned g_flag[2][8][32];   // [dir][group] flags, 128B apart

// ---------------------------------------------------------------------------
// init (grid 64): zero h buffers + flags, recover lengths[] in parallel.
// ---------------------------------------------------------------------------
__global__ void birnn_init_kernel(const void* __restrict__ maskraw) {
    const int b = blockIdx.x;       // 64 blocks, 256 threads
    const int tid = threadIdx.x;
    uint4* hz = (uint4*)&g_hA[0][0][0];
    hz[b * 512 + tid]       = make_uint4(0, 0, 0, 0);
    hz[b * 512 + 256 + tid] = make_uint4(0, 0, 0, 0);
    if (b == 0 && tid < 16) g_flag[tid >> 3][tid & 7][0] = 0u;

    __shared__ int s_cnt8, s_bad8, s_cnt32;
    if (tid == 0) { s_cnt8 = 0; s_bad8 = 0; s_cnt32 = 0; }
    __syncthreads();
    if (tid < 64) {
        const uchar4* m = (const uchar4*)((const unsigned char*)maskraw + b * 1024);
        int c = 0, bad = 0;
        #pragma unroll
        for (int j = 0; j < 4; ++j) {
            uchar4 v = m[tid * 4 + j];
            c   += (v.x != 0) + (v.y != 0) + (v.z != 0) + (v.w != 0);
            bad += (v.x > 1)  + (v.y > 1)  + (v.z > 1)  + (v.w > 1);
        }
        atomicAdd(&s_cnt8, c);
        if (bad) atomicAdd(&s_bad8, 1);
    }
    {
        const uint4* m = (const uint4*)((const unsigned*)maskraw + b * 1024);
        uint4 v = m[tid];
        int c = (v.x != 0u) + (v.y != 0u) + (v.z != 0u) + (v.w != 0u);
        atomicAdd(&s_cnt32, c);
    }
    __syncthreads();
    if (tid == 0) {
        const unsigned char* m8 = (const unsigned char*)maskraw + b * 1024;
        int cnt8 = s_cnt8;
        bool ok8 = (s_bad8 == 0) && (cnt8 >= Sk / 2);
        if (ok8) {
            if (m8[cnt8 - 1] == 0) ok8 = false;
            else if (cnt8 < Sk && m8[cnt8] != 0) ok8 = false;
        }
        g_len[b] = ok8 ? cnt8 : s_cnt32;
    }
}

// ---------------------------------------------------------------------------
// bf16 limb helpers
// ---------------------------------------------------------------------------
__device__ __forceinline__ unsigned short bf16hi(float v) {
    __nv_bfloat16 h = __float2bfloat16(v);
    return *(unsigned short*)&h;
}
__device__ __forceinline__ unsigned short bf16lo(float v) {
    __nv_bfloat16 h = __float2bfloat16(v);
    float r = v - __bfloat162float(h);
    __nv_bfloat16 l = __float2bfloat16(r);
    return *(unsigned short*)&l;
}

// ---------------------------------------------------------------------------
// x pre-conversion: fp32 -> bf16 limb fragments in mma register layout.
// ---------------------------------------------------------------------------
__global__ void birnn_xconv_kernel(const float* __restrict__ x) {
    const int s = blockIdx.x;
    const int tid = threadIdx.x;   // 256
    unsigned char* dst_base = g_xA + (size_t)s * XSTEP_B;
    for (int sl = tid; sl < 8192; sl += 256) {
        int t    = sl & 31;
        int wr   = (sl >> 5) & 3;
        int limb = (sl >> 7) & 1;
        int ks   = (sl >> 8) & 7;
        int ci   = sl >> 11;
        uint4 pk;
        unsigned* pq = (unsigned*)&pk;
        #pragma unroll
        for (int j = 0; j < 4; ++j) {
            int row = wr * 16 + (t >> 2) + 8 * (j & 1);
            int k   = (ci * 8 + ks) * 16 + (t & 3) * 2 + 8 * (j >> 1);
            float2 v = *(const float2*)&x[((size_t)row * Sk + s) * Dk + k];
            unsigned short u0 = limb ? bf16lo(v.x) : bf16hi(v.x);
            unsigned short u1 = limb ? bf16lo(v.y) : bf16hi(v.y);
            pq[j] = (unsigned)u0 | ((unsigned)u1 << 16);
        }
        *(uint4*)(dst_base + (size_t)ci * CHUNK32
                  + (uint32_t)((((ks * 2 + limb) * 4 + wr) * 32 + t) * 16)) = pk;
    }
}

// ---------------------------------------------------------------------------
__device__ __forceinline__ void mma16816(float* c, uint4 a,
                                         uint32_t b0, uint32_t b1) {
    asm volatile(
        "mma.sync.aligned.m16n8k16.row.col.f32.bf16.bf16.f32 "
        "{%0,%1,%2,%3}, {%4,%5,%6,%7}, {%8,%9}, {%0,%1,%2,%3};"
        : "+f"(c[0]), "+f"(c[1]), "+f"(c[2]), "+f"(c[3])
        : "r"(a.x), "r"(a.y), "r"(a.z), "r"(a.w), "r"(b0), "r"(b1));
}

// One 16KB A sub-chunk (4 k16-steps) from SMEM against resident W fragments.
__device__ __forceinline__ void mma_sub(
    const unsigned char* sa, const unsigned char* sw, int ksb,
    int wr, int nh, int lid, float a0[2][4], float a1[2][4]) {
    #pragma unroll
    for (int kl = 0; kl < 4; ++kl) {
        uint4 ahi = *(const uint4*)(sa +
            (uint32_t)((((kl * 2 + 0) * 4 + wr) * 32 + lid) * 16));
        uint4 alo = *(const uint4*)(sa +
            (uint32_t)((((kl * 2 + 1) * 4 + wr) * 32 + lid) * 16));
        int ksg = ksb + kl;
        uint4 bhi = *(const uint4*)(sw +
            (uint32_t)((((ksg * 2 + 0) * 2 + nh) * 32 + lid) * 16));
        uint4 blo = *(const uint4*)(sw +
            (uint32_t)((((ksg * 2 + 1) * 2 + nh) * 32 + lid) * 16));
        mma16816(a0[0], ahi, bhi.x, bhi.y);
        mma16816(a0[1], ahi, bhi.z, bhi.w);
        mma16816(a1[0], ahi, blo.x, blo.y);
        mma16816(a1[1], ahi, blo.z, blo.w);
        mma16816(a1[0], alo, bhi.x, bhi.y);
        mma16816(a1[1], alo, bhi.z, bhi.w);
    }
}

__device__ __forceinline__ float sigf(float x) {
    return 1.0f / (1.0f + __expf(-x));
}
__device__ __forceinline__ void flag_arrive(unsigned* p) {
    asm volatile("red.release.gpu.global.add.u32 [%0], 1;" :: "l"(p) : "memory");
}
__device__ __forceinline__ void flag_wait(const unsigned* p, unsigned target) {
    unsigned v;
    do {
        asm volatile("ld.acquire.gpu.global.u32 %0, [%1];"
                     : "=r"(v) : "l"(p) : "memory");
    } while (v < target);
}

// Build W fragments (32 ks, 2 limbs, 2 nh halves) from a 512-k window.
__device__ __forceinline__ void build_wfrags(
    unsigned char* sw, const float* w, int ubase, int tid) {
    for (int sl = tid; sl < 4096; sl += THREADS) {
        int t    = sl & 31;
        int nhs  = (sl >> 5) & 1;
        int limb = (sl >> 6) & 1;
        int ks   = sl >> 7;               // 0..31
        uint4 pk;
        unsigned* pq = (unsigned*)&pk;
        #pragma unroll
        for (int q = 0; q < 4; ++q) {
            int nf  = 2 * nhs + (q >> 1);
            int k   = ks * 16 + (t & 3) * 2 + (q & 1) * 8;   // 0..511
            int col = nf * 8 + (t >> 2);
            int gcol = ((col >> 3) << 9) + ubase + (col & 7);
            float v0 = w[(size_t)k * 2048 + gcol];
            float v1 = w[(size_t)(k + 1) * 2048 + gcol];
            unsigned short u0 = limb ? bf16lo(v0) : bf16hi(v0);
            unsigned short u1 = limb ? bf16lo(v1) : bf16hi(v1);
            pq[q] = (unsigned)u0 | ((unsigned)u1 << 16);
        }
        *(uint4*)(sw + (uint32_t)((((ks * 2 + limb) * 2 + nhs) * 32 + t) * 16)) = pk;
    }
}

// ---------------------------------------------------------------------------
// bulk x-GEMM: zx[dir][blk][s][b][32] = x @ Wx   (1024 blocks, no barriers)
// ---------------------------------------------------------------------------
extern __shared__ __align__(16) unsigned char smraw[];

__global__ void __launch_bounds__(THREADS, 1)
birnn_xgemm_kernel(const float* __restrict__ kern_f,
                   const float* __restrict__ kern_b) {
    const int tid = threadIdx.x;
    const int wid = tid >> 5, lid = tid & 31;
    const int wr = wid & 3, nh = wid >> 2;
    const int bx = blockIdx.x;
    const int dir = bx >> 9;
    const int blk = (bx >> 3) & 63;
    const int s0  = (bx & 7) * 128;
    const int ubase = blk * 8;

    build_wfrags(smraw + XG_W, dir ? kern_b : kern_f, ubase, tid);
    __syncthreads();

    uint32_t smem_u32 = (uint32_t)__cvta_generic_to_shared(smraw);

    auto stage = [&](int it) {
        const unsigned char* src = g_xA
            + (size_t)(s0 + (it >> 3)) * XSTEP_B + (uint32_t)(it & 7) * SUB_B;
        uint32_t dst = smem_u32 + XG_A + (uint32_t)(it & 3) * SUB_B;
        #pragma unroll
        for (int j = 0; j < 4; ++j) {     // 1024 x 16B / 256 threads
            uint32_t off = (uint32_t)(j * 256 + tid) * 16;
            asm volatile("cp.async.cg.shared.global [%0], [%1], 16;\n"
                         :: "r"(dst + off), "l"(src + off));
        }
        asm volatile("cp.async.commit_group;\n");
    };

    stage(0); stage(1); stage(2);

    float a0[2][4], a1[2][4];
    #pragma unroll 1
    for (int it = 0; it < 1024; ++it) {
        const int c = it & 7;
        if (c == 0) {
            #pragma unroll
            for (int f = 0; f < 2; ++f)
                #pragma unroll
                for (int i = 0; i < 4; ++i) { a0[f][i] = 0.0f; a1[f][i] = 0.0f; }
        }
        asm volatile("cp.async.wait_group 2;\n" ::: "memory");
        __syncthreads();
        if (it + 3 < 1024) stage(it + 3);
        else asm volatile("cp.async.commit_group;\n");
        mma_sub(smraw + XG_A + (uint32_t)(it & 3) * SUB_B, smraw + XG_W,
                c * 4, wr, nh, lid, a0, a1);
        if (c == 7) {
            const int sidx = s0 + (it >> 3);
            float* dst = &g_zx[dir][blk][sidx][0];
            #pragma unroll
            for (int f = 0; f < 2; ++f) {
                int row = wr * 16 + (lid >> 2);
                int col = (2 * nh + f) * 8 + (lid & 3) * 2;
                *(float2*)&dst[row * 32 + col] =
                    make_float2(a0[f][0] + a1[f][0], a0[f][1] + a1[f][1]);
                *(float2*)&dst[(row + 8) * 32 + col] =
                    make_float2(a0[f][2] + a1[f][2], a0[f][3] + a1[f][3]);
            }
        }
    }
}

// ---------------------------------------------------------------------------
// recurrent loop: 128 persistent blocks (64/dir), h-half GEMM only.
// Warp-autonomous MMA phase: A via direct LDG.cg + per-group flags.
// ---------------------------------------------------------------------------
__global__ void __launch_bounds__(THREADS, 1)
birnn_loop_kernel(const float* __restrict__ rkern_f,
                  const float* __restrict__ bias_f,
                  const float* __restrict__ rkern_b,
                  const float* __restrict__ bias_b,
                  float* __restrict__ out) {
    const int tid = threadIdx.x;
    const int wid = tid >> 5, lid = tid & 31;
    const int wr = wid & 3, nh = wid >> 2;
    const int dir = blockIdx.x >> 6;
    const int blk = blockIdx.x & 63;
    const int ubase = blk * 8;

    const float* rkern = dir ? rkern_b : rkern_f;
    const float* bias  = dir ? bias_b  : bias_f;

    uint32_t smem_u32 = (uint32_t)__cvta_generic_to_shared(smraw);
    float* zxS   = (float*)(smraw + LP_ZX);   // [64][40]
    float* zS    = (float*)(smraw + LP_Z);    // [64][34]
    float* sH    = (float*)(smraw + LP_H);    // [64][9]
    float* sC    = (float*)(smraw + LP_C);    // [64][9]
    float* biasS = (float*)(smraw + LP_BI);   // [32]
    int*   sLen  = (int*)(smraw + LP_LEN);

    build_wfrags(smraw + LP_W, rkern, ubase, tid);
    if (tid < 32) {
        int gcol = ((tid >> 3) << 9) + ubase + (tid & 7);
        biasS[tid] = bias[gcol];
    }
    for (int i = tid; i < Bk * 9; i += THREADS) { sH[i] = 0.0f; sC[i] = 0.0f; }
    if (tid < Bk) sLen[tid] = g_len[tid];
    __syncthreads();

    auto stage_zx = [&](int sidx) {
        const float* src = &g_zx[dir][blk][sidx][0];
        #pragma unroll
        for (int r = 0; r < 2; ++r) {
            int i = tid + r * THREADS;         // 512 x 16B
            int b = i >> 3, p = i & 7;
            uint32_t dst = smem_u32 + LP_ZX + (uint32_t)((b * 40 + p * 4) * 4);
            asm volatile("cp.async.cg.shared.global [%0], [%1], 16;\n"
                         :: "r"(dst), "l"(src + (b * 32 + p * 4)));
        }
        asm volatile("cp.async.commit_group;\n");
    };

    // load A fragments of sub-chunk c for this warp (8 x LDG.128, L2-coherent)
    auto ldA = [&](const unsigned char* hb, int c, uint4* A) {
        #pragma unroll
        for (int kl = 0; kl < 4; ++kl) {
            int ks = c * 4 + kl;
            A[kl * 2 + 0] = __ldcg((const uint4*)(hb +
                (uint32_t)((((ks * 2 + 0) * 4 + wr) * 32 + lid) * 16)));
            A[kl * 2 + 1] = __ldcg((const uint4*)(hb +
                (uint32_t)((((ks * 2 + 1) * 4 + wr) * 32 + lid) * 16)));
        }
    };

    // prologue: zx for step 0
    stage_zx(dir ? (Sk - 1) : 0);

    float a0[2][4], a1[2][4];

    for (int t = 0; t < Sk; ++t) {
        const int rp = t & 1, wp = rp ^ 1;
        const int sidx = dir ? (Sk - 1 - t) : t;
        const unsigned target = (unsigned)t * 8u;
        const unsigned char* hb = &g_hA[dir][rp][0];

        #pragma unroll
        for (int f = 0; f < 2; ++f)
            #pragma unroll
            for (int i = 0; i < 4; ++i) { a0[f][i] = 0.0f; a1[f][i] = 0.0f; }

        uint4 Ac[8], An[8];
        flag_wait(&g_flag[dir][0][0], target);
        ldA(hb, 0, Ac);

        #pragma unroll
        for (int c = 0; c < 8; ++c) {
            if (c < 7) {                      // depth-1 prefetch of next chunk
                flag_wait(&g_flag[dir][c + 1][0], target);
                ldA(hb, c + 1, An);
            }
            #pragma unroll
            for (int kl = 0; kl < 4; ++kl) {
                int ksg = c * 4 + kl;
                uint4 bhi = *(const uint4*)(smraw + LP_W +
                    (uint32_t)((((ksg * 2 + 0) * 2 + nh) * 32 + lid) * 16));
                uint4 blo = *(const uint4*)(smraw + LP_W +
                    (uint32_t)((((ksg * 2 + 1) * 2 + nh) * 32 + lid) * 16));
                uint4 ahi = Ac[kl * 2 + 0];
                uint4 alo = Ac[kl * 2 + 1];
                mma16816(a0[0], ahi, bhi.x, bhi.y);
                mma16816(a0[1], ahi, bhi.z, bhi.w);
                mma16816(a1[0], ahi, blo.x, blo.y);
                mma16816(a1[1], ahi, blo.z, blo.w);
                mma16816(a1[0], alo, bhi.x, bhi.y);
                mma16816(a1[1], alo, bhi.z, bhi.w);
            }
            #pragma unroll
            for (int j = 0; j < 8; ++j) Ac[j] = An[j];
        }

        // ---- accumulators -> zS ----
        #pragma unroll
        for (int f = 0; f < 2; ++f) {
            int row = wr * 16 + (lid >> 2);
            int col = (2 * nh + f) * 8 + (lid & 3) * 2;
            *(float2*)&zS[row * 34 + col] =
                make_float2(a0[f][0] + a1[f][0], a0[f][1] + a1[f][1]);
            *(float2*)&zS[(row + 8) * 34 + col] =
                make_float2(a0[f][2] + a1[f][2], a0[f][3] + a1[f][3]);
        }
        asm volatile("cp.async.wait_group 0;\n" ::: "memory");   // zx tile
        __syncthreads();

        // ---- gates, mask, state update (512 tasks) ----
        #pragma unroll
        for (int r = 0; r < 2; ++r) {
            int id = tid + r * THREADS;
            int ul = id & 7, b = id >> 3;
            float zi = zS[b * 34 + ul]      + zxS[b * 40 + ul]      + biasS[ul];
            float zf = zS[b * 34 + 8 + ul]  + zxS[b * 40 + 8 + ul]  + biasS[8 + ul];
            float zg = zS[b * 34 + 16 + ul] + zxS[b * 40 + 16 + ul] + biasS[16 + ul];
            float zo = zS[b * 34 + 24 + ul] + zxS[b * 40 + 24 + ul] + biasS[24 + ul];
            float cold = sC[b * 9 + ul];
            float cn = sigf(zf) * cold + sigf(zi) * tanhf(zg);
            float hn = sigf(zo) * tanhf(cn);
            bool act = sidx < sLen[b];
            sC[b * 9 + ul] = act ? cn : cold;
            sH[b * 9 + ul] = act ? hn : sH[b * 9 + ul];
        }
        __syncthreads();

        // ---- publish h limbs into fragment layout (flat ks = blk>>1) ----
        {
            unsigned char* hbw = &g_hA[dir][wp][0];
            const int ks_h = blk >> 1;
            #pragma unroll
            for (int r = 0; r < 2; ++r) {
                int id = tid + r * THREADS;        // 512 tasks: (p, limb, b)
                int p = id & 3, limb = (id >> 2) & 1, b = id >> 3;
                float v0 = sH[b * 9 + 2 * p];
                float v1 = sH[b * 9 + 2 * p + 1];
                unsigned short u0 = limb ? bf16lo(v0) : bf16hi(v0);
                unsigned short u1 = limb ? bf16lo(v1) : bf16hi(v1);
                unsigned val = (unsigned)u0 | ((unsigned)u1 << 16);
                int tslot = (b & 7) * 4 + p;
                int j = ((b >> 3) & 1) + 2 * (blk & 1);
                unsigned* dst = (unsigned*)(hbw +
                    (uint32_t)((((ks_h * 2 + limb) * 4 + (b >> 4)) * 32 + tslot) * 16
                               + j * 4));
                __stcg(dst, val);
            }
        }
        __syncthreads();

        // arrive on this block's group flag (release publishes stcg writes)
        if (tid == 0) flag_arrive(&g_flag[dir][blk >> 3][0]);

        // ---- off critical path: out stores + zx prefetch for t+1 ----
        #pragma unroll
        for (int r = 0; r < 2; ++r) {
            int id = tid + r * THREADS;
            int ul = id & 7, b = id >> 3;
            out[((size_t)b * Sk + sidx) * (2 * Uk) + dir * Uk + ubase + ul]
                = sH[b * 9 + ul];
        }
        if (t + 1 < Sk) stage_zx(dir ? (Sk - 2 - t) : (t + 1));
    }

    // ---- final states: h_f, c_f, h_b, c_b ----
    const size_t obase = (size_t)Bk * Sk * (2 * Uk);
    #pragma unroll
    for (int r = 0; r < 2; ++r) {
        int id = tid + r * THREADS;
        int ul = id & 7, b = id >> 3;
        int ug = ubase + ul;
        size_t doff = obase + (size_t)dir * 2 * Bk * Uk;
        out[doff + (size_t)b * Uk + ug] = sH[b * 9 + ul];
        out[doff + (size_t)Bk * Uk + (size_t)b * Uk + ug] = sC[b * 9 + ul];
    }
}

// ---------------------------------------------------------------------------
extern "C" void kernel_launch(void* const* d_in, const int* in_sizes, int n_in,
                              void* d_out, int out_size) {
    const float* x    = (const float*)d_in[0];
    const void*  mask = d_in[1];
    const float* kf   = (const float*)d_in[2];
    const float* rkf  = (const float*)d_in[3];
    const float* bf   = (const float*)d_in[4];
    const float* kb   = (const float*)d_in[5];
    const float* rkb  = (const float*)d_in[6];
    const float* bb   = (const float*)d_in[7];
    float* out = (float*)d_out;

    cudaFuncSetAttribute(birnn_xgemm_kernel,
                         cudaFuncAttributeMaxDynamicSharedMemorySize, XG_SMEM);
    cudaFuncSetAttribute(birnn_loop_kernel,
                         cudaFuncAttributeMaxDynamicSharedMemorySize, LP_SMEM);

    birnn_init_kernel<<<64, 256>>>(mask);
    birnn_xconv_kernel<<<Sk, 256>>>(x);
    birnn_xgemm_kernel<<<1024, THREADS, XG_SMEM>>>(kf, kb);
    birnn_loop_kernel<<<2 * NBLK_DIR, THREADS, LP_SMEM>>>(
        rkf, bf, rkb, bb, out);
}

// round 15
// speedup vs baseline: 1.0363x; 1.0363x over previous
#include <cuda_runtime.h>
#include <cuda_bf16.h>
#include <cstdint>

// ---------------------------------------------------------------------------
// BiRNN (bidirectional masked LSTM), B=64, S=1024, D=U=512.
// Split design:
//   1) birnn_xconv : x -> bf16 limb fragments (mma register layout) in g_xA
//   2) birnn_xgemm : zx = x @ Wx for ALL timesteps (bulk GEMM, 1024 blocks)
//   3) birnn_loop  : sequential recurrence, h-half GEMM only (K=512).
//      64 persistent blocks, EACH handles BOTH directions (fwd step t, then
//      bwd step t): the grid-barrier latency of one direction hides behind
//      the other direction's compute. One wait + one arrive per iteration.
// mma.sync m16n8k16 bf16 with limb-split (3 products) -> fp32-grade accuracy.
// ---------------------------------------------------------------------------

namespace {
constexpr int Bk = 64;
constexpr int Sk = 1024;
constexpr int Dk = 512;
constexpr int Uk = 512;
constexpr int THREADS  = 256;          // 8 warps: wr = wid&3 (M16), nh = wid>>2 (N16)
constexpr int NBLK     = 64;           // loop blocks (each does both dirs)
constexpr uint32_t SUB_B   = 16384;    // 16KB sub-chunk = 4 k16-steps
constexpr uint32_t CHUNK32 = 32768;    // xconv 32KB chunk granularity
constexpr uint32_t XSTEP_B = 131072;   // x fragments per timestep (32 ks)

// xgemm smem layout (bytes)
constexpr uint32_t XG_W    = 0;        // W-x frags: 32ks x2limb x2nh x32 x16B = 64KB
constexpr uint32_t XG_A    = 65536;    // ring: 4 x 16KB
constexpr uint32_t XG_SMEM = 131072;

// loop smem layout (bytes)
constexpr uint32_t LP_W    = 0;        // W-h frags, 2 dirs: 2 x 64KB
constexpr uint32_t LP_A    = 131072;   // ring: 3 x 16KB
constexpr uint32_t LP_ZX   = 180224;   // zx tiles, 2 dirs: 2 x [64][40] f32
constexpr uint32_t LP_Z    = 200704;   // zS [64][34] f32 = 8704
constexpr uint32_t LP_H    = 209408;   // sH 2 x [64][9] f32
constexpr uint32_t LP_C    = 214016;   // sC 2 x [64][9] f32
constexpr uint32_t LP_BI   = 218624;   // bias 2 x [32] f32
constexpr uint32_t LP_LEN  = 218880;   // lengths [64] int
constexpr uint32_t LP_SMEM = 219136;   // < 227KB
}

// persistent device state
__device__ __align__(16) unsigned char g_xA[(size_t)Sk * XSTEP_B];   // 128 MB
__device__ __align__(16) unsigned char g_hA[2][2][XSTEP_B];          // 512 KB
__device__ float    g_zx[2][NBLK][Sk][Bk * 32];                      // 1 GB
__device__ int      g_len[Bk];
__device__ unsigned g_bar;

// ---------------------------------------------------------------------------
// init (grid 64): zero h buffers + barrier, recover lengths[] in parallel.
// ---------------------------------------------------------------------------
__global__ void birnn_init_kernel(const void* __restrict__ maskraw) {
    const int b = blockIdx.x;       // 64 blocks, 256 threads
    const int tid = threadIdx.x;
    uint4* hz = (uint4*)&g_hA[0][0][0];
    hz[b * 512 + tid]       = make_uint4(0, 0, 0, 0);
    hz[b * 512 + 256 + tid] = make_uint4(0, 0, 0, 0);
    if (b == 0 && tid == 0) g_bar = 0u;

    __shared__ int s_cnt8, s_bad8, s_cnt32;
    if (tid == 0) { s_cnt8 = 0; s_bad8 = 0; s_cnt32 = 0; }
    __syncthreads();
    if (tid < 64) {
        const uchar4* m = (const uchar4*)((const unsigned char*)maskraw + b * 1024);
        int c = 0, bad = 0;
        #pragma unroll
        for (int j = 0; j < 4; ++j) {
            uchar4 v = m[tid * 4 + j];
            c   += (v.x != 0) + (v.y != 0) + (v.z != 0) + (v.w != 0);
            bad += (v.x > 1)  + (v.y > 1)  + (v.z > 1)  + (v.w > 1);
        }
        atomicAdd(&s_cnt8, c);
        if (bad) atomicAdd(&s_bad8, 1);
    }
    {
        const uint4* m = (const uint4*)((const unsigned*)maskraw + b * 1024);
        uint4 v = m[tid];
        int c = (v.x != 0u) + (v.y != 0u) + (v.z != 0u) + (v.w != 0u);
        atomicAdd(&s_cnt32, c);
    }
    __syncthreads();
    if (tid == 0) {
        const unsigned char* m8 = (const unsigned char*)maskraw + b * 1024;
        int cnt8 = s_cnt8;
        bool ok8 = (s_bad8 == 0) && (cnt8 >= Sk / 2);
        if (ok8) {
            if (m8[cnt8 - 1] == 0) ok8 = false;
            else if (cnt8 < Sk && m8[cnt8] != 0) ok8 = false;
        }
        g_len[b] = ok8 ? cnt8 : s_cnt32;
    }
}

// ---------------------------------------------------------------------------
// bf16 limb helpers
// ---------------------------------------------------------------------------
__device__ __forceinline__ unsigned short bf16hi(float v) {
    __nv_bfloat16 h = __float2bfloat16(v);
    return *(unsigned short*)&h;
}
__device__ __forceinline__ unsigned short bf16lo(float v) {
    __nv_bfloat16 h = __float2bfloat16(v);
    float r = v - __bfloat162float(h);
    __nv_bfloat16 l = __float2bfloat16(r);
    return *(unsigned short*)&l;
}

// ---------------------------------------------------------------------------
// x pre-conversion: fp32 -> bf16 limb fragments in mma register layout.
// ---------------------------------------------------------------------------
__global__ void birnn_xconv_kernel(const float* __restrict__ x) {
    const int s = blockIdx.x;
    const int tid = threadIdx.x;   // 256
    unsigned char* dst_base = g_xA + (size_t)s * XSTEP_B;
    for (int sl = tid; sl < 8192; sl += 256) {
        int t    = sl & 31;
        int wr   = (sl >> 5) & 3;
        int limb = (sl >> 7) & 1;
        int ks   = (sl >> 8) & 7;
        int ci   = sl >> 11;
        uint4 pk;
        unsigned* pq = (unsigned*)&pk;
        #pragma unroll
        for (int j = 0; j < 4; ++j) {
            int row = wr * 16 + (t >> 2) + 8 * (j & 1);
            int k   = (ci * 8 + ks) * 16 + (t & 3) * 2 + 8 * (j >> 1);
            float2 v = *(const float2*)&x[((size_t)row * Sk + s) * Dk + k];
            unsigned short u0 = limb ? bf16lo(v.x) : bf16hi(v.x);
            unsigned short u1 = limb ? bf16lo(v.y) : bf16hi(v.y);
            pq[j] = (unsigned)u0 | ((unsigned)u1 << 16);
        }
        *(uint4*)(dst_base + (size_t)ci * CHUNK32
                  + (uint32_t)((((ks * 2 + limb) * 4 + wr) * 32 + t) * 16)) = pk;
    }
}

// ---------------------------------------------------------------------------
__device__ __forceinline__ void mma16816(float* c, uint4 a,
                                         uint32_t b0, uint32_t b1) {
    asm volatile(
        "mma.sync.aligned.m16n8k16.row.col.f32.bf16.bf16.f32 "
        "{%0,%1,%2,%3}, {%4,%5,%6,%7}, {%8,%9}, {%0,%1,%2,%3};"
        : "+f"(c[0]), "+f"(c[1]), "+f"(c[2]), "+f"(c[3])
        : "r"(a.x), "r"(a.y), "r"(a.z), "r"(a.w), "r"(b0), "r"(b1));
}

// One 16KB A sub-chunk (4 k16-steps) from SMEM against resident W fragments.
__device__ __forceinline__ void mma_sub(
    const unsigned char* sa, const unsigned char* sw, int ksb,
    int wr, int nh, int lid, float a0[2][4], float a1[2][4]) {
    #pragma unroll
    for (int kl = 0; kl < 4; ++kl) {
        uint4 ahi = *(const uint4*)(sa +
            (uint32_t)((((kl * 2 + 0) * 4 + wr) * 32 + lid) * 16));
        uint4 alo = *(const uint4*)(sa +
            (uint32_t)((((kl * 2 + 1) * 4 + wr) * 32 + lid) * 16));
        int ksg = ksb + kl;
        uint4 bhi = *(const uint4*)(sw +
            (uint32_t)((((ksg * 2 + 0) * 2 + nh) * 32 + lid) * 16));
        uint4 blo = *(const uint4*)(sw +
            (uint32_t)((((ksg * 2 + 1) * 2 + nh) * 32 + lid) * 16));
        mma16816(a0[0], ahi, bhi.x, bhi.y);
        mma16816(a0[1], ahi, bhi.z, bhi.w);
        mma16816(a1[0], ahi, blo.x, blo.y);
        mma16816(a1[1], ahi, blo.z, blo.w);
        mma16816(a1[0], alo, bhi.x, bhi.y);
        mma16816(a1[1], alo, bhi.z, bhi.w);
    }
}

__device__ __forceinline__ float sigf(float x) {
    return 1.0f / (1.0f + __expf(-x));
}
__device__ __forceinline__ void bar_arrive(unsigned* p) {
    asm volatile("red.release.gpu.global.add.u32 [%0], 1;" :: "l"(p) : "memory");
}
__device__ __forceinline__ void bar_wait(const unsigned* p, unsigned target) {
    unsigned v;
    do {
        asm volatile("ld.acquire.gpu.global.u32 %0, [%1];"
                     : "=r"(v) : "l"(p) : "memory");
    } while (v < target);
}

// Build W fragments (32 ks, 2 limbs, 2 nh halves) from a 512-k window.
__device__ __forceinline__ void build_wfrags(
    unsigned char* sw, const float* w, int ubase, int tid) {
    for (int sl = tid; sl < 4096; sl += THREADS) {
        int t    = sl & 31;
        int nhs  = (sl >> 5) & 1;
        int limb = (sl >> 6) & 1;
        int ks   = sl >> 7;               // 0..31
        uint4 pk;
        unsigned* pq = (unsigned*)&pk;
        #pragma unroll
        for (int q = 0; q < 4; ++q) {
            int nf  = 2 * nhs + (q >> 1);
            int k   = ks * 16 + (t & 3) * 2 + (q & 1) * 8;   // 0..511
            int col = nf * 8 + (t >> 2);
            int gcol = ((col >> 3) << 9) + ubase + (col & 7);
            float v0 = w[(size_t)k * 2048 + gcol];
            float v1 = w[(size_t)(k + 1) * 2048 + gcol];
            unsigned short u0 = limb ? bf16lo(v0) : bf16hi(v0);
            unsigned short u1 = limb ? bf16lo(v1) : bf16hi(v1);
            pq[q] = (unsigned)u0 | ((unsigned)u1 << 16);
        }
        *(uint4*)(sw + (uint32_t)((((ks * 2 + limb) * 2 + nhs) * 32 + t) * 16)) = pk;
    }
}

// ---------------------------------------------------------------------------
// bulk x-GEMM: zx[dir][blk][s][b][32] = x @ Wx   (1024 blocks, no barriers)
// ---------------------------------------------------------------------------
extern __shared__ __align__(16) unsigned char smraw[];

__global__ void __launch_bounds__(THREADS, 1)
birnn_xgemm_kernel(const float* __restrict__ kern_f,
                   const float* __restrict__ kern_b) {
    const int tid = threadIdx.x;
    const int wid = tid >> 5, lid = tid & 31;
    const int wr = wid & 3, nh = wid >> 2;
    const int bx = blockIdx.x;
    const int dir = bx >> 9;
    const int blk = (bx >> 3) & 63;
    const int s0  = (bx & 7) * 128;
    const int ubase = blk * 8;

    build_wfrags(smraw + XG_W, dir ? kern_b : kern_f, ubase, tid);
    __syncthreads();

    uint32_t smem_u32 = (uint32_t)__cvta_generic_to_shared(smraw);

    auto stage = [&](int it) {
        const unsigned char* src = g_xA
            + (size_t)(s0 + (it >> 3)) * XSTEP_B + (uint32_t)(it & 7) * SUB_B;
        uint32_t dst = smem_u32 + XG_A + (uint32_t)(it & 3) * SUB_B;
        #pragma unroll
        for (int j = 0; j < 4; ++j) {     // 1024 x 16B / 256 threads
            uint32_t off = (uint32_t)(j * 256 + tid) * 16;
            asm volatile("cp.async.cg.shared.global [%0], [%1], 16;\n"
                         :: "r"(dst + off), "l"(src + off));
        }
        asm volatile("cp.async.commit_group;\n");
    };

    stage(0); stage(1); stage(2);

    float a0[2][4], a1[2][4];
    #pragma unroll 1
    for (int it = 0; it < 1024; ++it) {
        const int c = it & 7;
        if (c == 0) {
            #pragma unroll
            for (int f = 0; f < 2; ++f)
                #pragma unroll
                for (int i = 0; i < 4; ++i) { a0[f][i] = 0.0f; a1[f][i] = 0.0f; }
        }
        asm volatile("cp.async.wait_group 2;\n" ::: "memory");
        __syncthreads();
        if (it + 3 < 1024) stage(it + 3);
        else asm volatile("cp.async.commit_group;\n");
        mma_sub(smraw + XG_A + (uint32_t)(it & 3) * SUB_B, smraw + XG_W,
                c * 4, wr, nh, lid, a0, a1);
        if (c == 7) {
            const int sidx = s0 + (it >> 3);
            float* dst = &g_zx[dir][blk][sidx][0];
            #pragma unroll
            for (int f = 0; f < 2; ++f) {
                int row = wr * 16 + (lid >> 2);
                int col = (2 * nh + f) * 8 + (lid & 3) * 2;
                *(float2*)&dst[row * 32 + col] =
                    make_float2(a0[f][0] + a1[f][0], a0[f][1] + a1[f][1]);
                *(float2*)&dst[(row + 8) * 32 + col] =
                    make_float2(a0[f][2] + a1[f][2], a0[f][3] + a1[f][3]);
            }
        }
    }
}

// ---------------------------------------------------------------------------
// recurrent loop: 64 persistent blocks, each handles BOTH directions.
// ---------------------------------------------------------------------------
__global__ void __launch_bounds__(THREADS, 1)
birnn_loop_kernel(const float* __restrict__ rkern_f,
                  const float* __restrict__ bias_f,
                  const float* __restrict__ rkern_b,
                  const float* __restrict__ bias_b,
                  float* __restrict__ out) {
    const int tid = threadIdx.x;
    const int wid = tid >> 5, lid = tid & 31;
    const int wr = wid & 3, nh = wid >> 2;
    const int blk = blockIdx.x;        // 0..63
    const int ubase = blk * 8;

    uint32_t smem_u32 = (uint32_t)__cvta_generic_to_shared(smraw);
    float* zS    = (float*)(smraw + LP_Z);    // [64][34]
    int*   sLen  = (int*)(smraw + LP_LEN);

    build_wfrags(smraw + LP_W,         rkern_f, ubase, tid);
    build_wfrags(smraw + LP_W + 65536, rkern_b, ubase, tid);
    if (tid < 64) {
        int d = tid >> 5, c = tid & 31;
        int gcol = ((c >> 3) << 9) + ubase + (c & 7);
        ((float*)(smraw + LP_BI))[d * 32 + c] = (d ? bias_b : bias_f)[gcol];
    }
    for (int i = tid; i < 2 * Bk * 9; i += THREADS) {
        ((float*)(smraw + LP_H))[i] = 0.0f;
        ((float*)(smraw + LP_C))[i] = 0.0f;
    }
    if (tid < Bk) sLen[tid] = g_len[tid];
    __syncthreads();

    auto stage_h = [&](int dir, int c, int rp) {
        const unsigned char* src = &g_hA[dir][rp][0] + (uint32_t)c * SUB_B;
        uint32_t dst = smem_u32 + LP_A + (uint32_t)(c % 3) * SUB_B;
        #pragma unroll
        for (int j = 0; j < 4; ++j) {
            uint32_t off = (uint32_t)(j * 256 + tid) * 16;
            asm volatile("cp.async.cg.shared.global [%0], [%1], 16;\n"
                         :: "r"(dst + off), "l"(src + off));
        }
        asm volatile("cp.async.commit_group;\n");
    };
    auto stage_zx = [&](int dir, int sidx) {
        const float* src = &g_zx[dir][blk][sidx][0];
        #pragma unroll
        for (int r = 0; r < 2; ++r) {
            int i = tid + r * THREADS;         // 512 x 16B
            int b = i >> 3, p = i & 7;
            uint32_t dst = smem_u32 + LP_ZX + (uint32_t)dir * 10240u
                         + (uint32_t)((b * 40 + p * 4) * 4);
            asm volatile("cp.async.cg.shared.global [%0], [%1], 16;\n"
                         :: "r"(dst), "l"(src + (b * 32 + p * 4)));
        }
        asm volatile("cp.async.commit_group;\n");
    };

    // prologue: zx tiles for step 0 of both directions
    stage_zx(0, 0);
    stage_zx(1, Sk - 1);

    float a0[2][4], a1[2][4];

    for (int t = 0; t < Sk; ++t) {
        const int rp = t & 1, wp = rp ^ 1;

        // one wait covers both directions' h(t-1)
        if (tid == 0) bar_wait(&g_bar, (unsigned)t * (unsigned)NBLK);
        __syncthreads();

        #pragma unroll 1
        for (int dir = 0; dir < 2; ++dir) {
            const int sidx = dir ? (Sk - 1 - t) : t;
            const unsigned char* sw = smraw + LP_W + (uint32_t)dir * 65536u;
            float* zxS   = (float*)(smraw + LP_ZX + (uint32_t)dir * 10240u);
            float* sH    = (float*)(smraw + LP_H + (uint32_t)dir * 2304u);
            float* sC    = (float*)(smraw + LP_C + (uint32_t)dir * 2304u);
            float* biasS = (float*)(smraw + LP_BI) + dir * 32;

            stage_h(dir, 0, rp);
            stage_h(dir, 1, rp);

            #pragma unroll
            for (int f = 0; f < 2; ++f)
                #pragma unroll
                for (int i = 0; i < 4; ++i) { a0[f][i] = 0.0f; a1[f][i] = 0.0f; }

            #pragma unroll 1
            for (int c = 0; c < 8; ++c) {
                if (c < 7)
                    asm volatile("cp.async.wait_group 1;\n" ::: "memory");
                else
                    asm volatile("cp.async.wait_group 0;\n" ::: "memory");
                __syncthreads();
                if (c < 6) stage_h(dir, c + 2, rp);
                mma_sub(smraw + LP_A + (uint32_t)(c % 3) * SUB_B, sw,
                        c * 4, wr, nh, lid, a0, a1);
            }

            // ---- accumulators -> zS ----
            #pragma unroll
            for (int f = 0; f < 2; ++f) {
                int row = wr * 16 + (lid >> 2);
                int col = (2 * nh + f) * 8 + (lid & 3) * 2;
                *(float2*)&zS[row * 34 + col] =
                    make_float2(a0[f][0] + a1[f][0], a0[f][1] + a1[f][1]);
                *(float2*)&zS[(row + 8) * 34 + col] =
                    make_float2(a0[f][2] + a1[f][2], a0[f][3] + a1[f][3]);
            }
            __syncthreads();

            // ---- gates, mask, state update (512 tasks) ----
            #pragma unroll
            for (int r = 0; r < 2; ++r) {
                int id = tid + r * THREADS;
                int ul = id & 7, b = id >> 3;
                float zi = zS[b * 34 + ul]      + zxS[b * 40 + ul]      + biasS[ul];
                float zf = zS[b * 34 + 8 + ul]  + zxS[b * 40 + 8 + ul]  + biasS[8 + ul];
                float zg = zS[b * 34 + 16 + ul] + zxS[b * 40 + 16 + ul] + biasS[16 + ul];
                float zo = zS[b * 34 + 24 + ul] + zxS[b * 40 + 24 + ul] + biasS[24 + ul];
                float cold = sC[b * 9 + ul];
                float cn = sigf(zf) * cold + sigf(zi) * tanhf(zg);
                float hn = sigf(zo) * tanhf(cn);
                bool act = sidx < sLen[b];
                sC[b * 9 + ul] = act ? cn : cold;
                sH[b * 9 + ul] = act ? hn : sH[b * 9 + ul];
            }
            __syncthreads();

            // ---- publish h limbs into fragment layout (flat ks = blk>>1) ----
            {
                unsigned char* hbw = &g_hA[dir][wp][0];
                const int ks_h = blk >> 1;
                #pragma unroll
                for (int r = 0; r < 2; ++r) {
                    int id = tid + r * THREADS;        // 512 tasks: (p, limb, b)
                    int p = id & 3, limb = (id >> 2) & 1, b = id >> 3;
                    float v0 = sH[b * 9 + 2 * p];
                    float v1 = sH[b * 9 + 2 * p + 1];
                    unsigned short u0 = limb ? bf16lo(v0) : bf16hi(v0);
                    unsigned short u1 = limb ? bf16lo(v1) : bf16hi(v1);
                    unsigned val = (unsigned)u0 | ((unsigned)u1 << 16);
                    int tslot = (b & 7) * 4 + p;
                    int j = ((b >> 3) & 1) + 2 * (blk & 1);
                    unsigned* dst = (unsigned*)(hbw +
                        (uint32_t)((((ks_h * 2 + limb) * 4 + (b >> 4)) * 32 + tslot) * 16
                                   + j * 4));
                    __stcg(dst, val);
                }
            }

            // ---- out stores for this direction ----
            #pragma unroll
            for (int r = 0; r < 2; ++r) {
                int id = tid + r * THREADS;
                int ul = id & 7, b = id >> 3;
                out[((size_t)b * Sk + sidx) * (2 * Uk) + dir * Uk + ubase + ul]
                    = sH[b * 9 + ul];
            }
            __syncthreads();
        }

        // single arrive per iteration (release publishes both dirs' stcg)
        if (tid == 0) bar_arrive(&g_bar);

        // ---- off critical path: zx prefetch for t+1, both dirs ----
        if (t + 1 < Sk) {
            stage_zx(0, t + 1);
            stage_zx(1, Sk - 2 - t);
        }
    }

    // ---- final states: h_f, c_f, h_b, c_b ----
    const size_t obase = (size_t)Bk * Sk * (2 * Uk);
    #pragma unroll 1
    for (int dir = 0; dir < 2; ++dir) {
        float* sH = (float*)(smraw + LP_H + (uint32_t)dir * 2304u);
        float* sC = (float*)(smraw + LP_C + (uint32_t)dir * 2304u);
        #pragma unroll
        for (int r = 0; r < 2; ++r) {
            int id = tid + r * THREADS;
            int ul = id & 7, b = id >> 3;
            int ug = ubase + ul;
            size_t doff = obase + (size_t)dir * 2 * Bk * Uk;
            out[doff + (size_t)b * Uk + ug] = sH[b * 9 + ul];
            out[doff + (size_t)Bk * Uk + (size_t)b * Uk + ug] = sC[b * 9 + ul];
        }
    }
}

// ---------------------------------------------------------------------------
extern "C" void kernel_launch(void* const* d_in, const int* in_sizes, int n_in,
                              void* d_out, int out_size) {
    const float* x    = (const float*)d_in[0];
    const void*  mask = d_in[1];
    const float* kf   = (const float*)d_in[2];
    const float* rkf  = (const float*)d_in[3];
    const float* bf   = (const float*)d_in[4];
    const float* kb   = (const float*)d_in[5];
    const float* rkb  = (const float*)d_in[6];
    const float* bb   = (const float*)d_in[7];
    float* out = (float*)d_out;

    cudaFuncSetAttribute(birnn_xgemm_kernel,
                         cudaFuncAttributeMaxDynamicSharedMemorySize, XG_SMEM);
    cudaFuncSetAttribute(birnn_loop_kernel,
                         cudaFuncAttributeMaxDynamicSharedMemorySize, LP_SMEM);

    birnn_init_kernel<<<64, 256>>>(mask);
    birnn_xconv_kernel<<<Sk, 256>>>(x);
    birnn_xgemm_kernel<<<1024, THREADS, XG_SMEM>>>(kf, kb);
    birnn_loop_kernel<<<NBLK, THREADS, LP_SMEM>>>(
        rkf, bf, rkb, bb, out);
}

// round 16
// speedup vs baseline: 1.1917x; 1.1500x over previous
#include <cuda_runtime.h>
#include <cuda_bf16.h>
#include <cstdint>

// ---------------------------------------------------------------------------
// BiRNN (bidirectional masked LSTM), B=64, S=1024, D=U=512.
// Split design (R13 structure, 512-thread / 16-warp blocks, n8 per warp):
//   1) birnn_xconv : x -> bf16 limb fragments (mma register layout) in g_xA
//   2) birnn_xgemm : zx = x @ Wx for ALL timesteps (bulk GEMM, 1024 blocks)
//   3) birnn_loop  : sequential recurrence, h-half GEMM only (K=512),
//                    128 persistent blocks (64/dir), per-dir grid barrier.
// mma.sync m16n8k16 bf16 with limb-split (3 products) -> fp32-grade accuracy.
// ---------------------------------------------------------------------------

namespace {
constexpr int Bk = 64;
constexpr int Sk = 1024;
constexpr int Dk = 512;
constexpr int Uk = 512;
constexpr int THREADS  = 512;          // 16 warps: wr = wid&3 (M16), nf = wid>>2 (N8)
constexpr int NBLK_DIR = 64;
constexpr uint32_t SUB_B   = 16384;    // 16KB sub-chunk = 4 k16-steps
constexpr uint32_t CHUNK32 = 32768;    // xconv 32KB chunk granularity
constexpr uint32_t XSTEP_B = 131072;   // x fragments per timestep (32 ks)

// xgemm smem layout (bytes)
constexpr uint32_t XG_W    = 0;        // W-x frags: 32ks x2limb x2nh x32 x16B = 64KB
constexpr uint32_t XG_A    = 65536;    // ring: 4 x 16KB
constexpr uint32_t XG_SMEM = 131072;

// loop smem layout (bytes)
constexpr uint32_t LP_W    = 0;        // W-h frags: 64KB
constexpr uint32_t LP_A    = 65536;    // ring: 4 x 16KB
constexpr uint32_t LP_ZX   = 131072;   // zx tile [64][40] f32 = 10240
constexpr uint32_t LP_Z    = 141312;   // zS [64][34] f32 = 8704
constexpr uint32_t LP_H    = 150016;   // sH [64][9] f32 = 2304
constexpr uint32_t LP_C    = 152320;   // sC [64][9] f32 = 2304
constexpr uint32_t LP_BI   = 154624;   // bias [32] f32
constexpr uint32_t LP_LEN  = 154752;   // lengths [64] int
constexpr uint32_t LP_SMEM = 155008;
}

// persistent device state
__device__ __align__(16) unsigned char g_xA[(size_t)Sk * XSTEP_B];   // 128 MB
__device__ __align__(16) unsigned char g_hA[2][2][XSTEP_B];          // 512 KB
__device__ float    g_zx[2][NBLK_DIR][Sk][Bk * 32];                  // 1 GB
__device__ int      g_len[Bk];
__device__ unsigned g_bar[2][32];      // per-dir counters, 128B apart

// ---------------------------------------------------------------------------
// init (grid 64): zero h buffers + barriers, recover lengths[] in parallel.
// ---------------------------------------------------------------------------
__global__ void birnn_init_kernel(const void* __restrict__ maskraw) {
    const int b = blockIdx.x;       // 64 blocks, 256 threads
    const int tid = threadIdx.x;
    uint4* hz = (uint4*)&g_hA[0][0][0];
    hz[b * 512 + tid]       = make_uint4(0, 0, 0, 0);
    hz[b * 512 + 256 + tid] = make_uint4(0, 0, 0, 0);
    if (b == 0 && tid < 2) g_bar[tid][0] = 0u;

    __shared__ int s_cnt8, s_bad8, s_cnt32;
    if (tid == 0) { s_cnt8 = 0; s_bad8 = 0; s_cnt32 = 0; }
    __syncthreads();
    if (tid < 64) {
        const uchar4* m = (const uchar4*)((const unsigned char*)maskraw + b * 1024);
        int c = 0, bad = 0;
        #pragma unroll
        for (int j = 0; j < 4; ++j) {
            uchar4 v = m[tid * 4 + j];
            c   += (v.x != 0) + (v.y != 0) + (v.z != 0) + (v.w != 0);
            bad += (v.x > 1)  + (v.y > 1)  + (v.z > 1)  + (v.w > 1);
        }
        atomicAdd(&s_cnt8, c);
        if (bad) atomicAdd(&s_bad8, 1);
    }
    {
        const uint4* m = (const uint4*)((const unsigned*)maskraw + b * 1024);
        uint4 v = m[tid];
        int c = (v.x != 0u) + (v.y != 0u) + (v.z != 0u) + (v.w != 0u);
        atomicAdd(&s_cnt32, c);
    }
    __syncthreads();
    if (tid == 0) {
        const unsigned char* m8 = (const unsigned char*)maskraw + b * 1024;
        int cnt8 = s_cnt8;
        bool ok8 = (s_bad8 == 0) && (cnt8 >= Sk / 2);
        if (ok8) {
            if (m8[cnt8 - 1] == 0) ok8 = false;
            else if (cnt8 < Sk && m8[cnt8] != 0) ok8 = false;
        }
        g_len[b] = ok8 ? cnt8 : s_cnt32;
    }
}

// ---------------------------------------------------------------------------
// bf16 limb helpers
// ---------------------------------------------------------------------------
__device__ __forceinline__ unsigned short bf16hi(float v) {
    __nv_bfloat16 h = __float2bfloat16(v);
    return *(unsigned short*)&h;
}
__device__ __forceinline__ unsigned short bf16lo(float v) {
    __nv_bfloat16 h = __float2bfloat16(v);
    float r = v - __bfloat162float(h);
    __nv_bfloat16 l = __float2bfloat16(r);
    return *(unsigned short*)&l;
}

// ---------------------------------------------------------------------------
// x pre-conversion: fp32 -> bf16 limb fragments in mma register layout.
// ---------------------------------------------------------------------------
__global__ void birnn_xconv_kernel(const float* __restrict__ x) {
    const int s = blockIdx.x;
    const int tid = threadIdx.x;   // 256
    unsigned char* dst_base = g_xA + (size_t)s * XSTEP_B;
    for (int sl = tid; sl < 8192; sl += 256) {
        int t    = sl & 31;
        int wr   = (sl >> 5) & 3;
        int limb = (sl >> 7) & 1;
        int ks   = (sl >> 8) & 7;
        int ci   = sl >> 11;
        uint4 pk;
        unsigned* pq = (unsigned*)&pk;
        #pragma unroll
        for (int j = 0; j < 4; ++j) {
            int row = wr * 16 + (t >> 2) + 8 * (j & 1);
            int k   = (ci * 8 + ks) * 16 + (t & 3) * 2 + 8 * (j >> 1);
            float2 v = *(const float2*)&x[((size_t)row * Sk + s) * Dk + k];
            unsigned short u0 = limb ? bf16lo(v.x) : bf16hi(v.x);
            unsigned short u1 = limb ? bf16lo(v.y) : bf16hi(v.y);
            pq[j] = (unsigned)u0 | ((unsigned)u1 << 16);
        }
        *(uint4*)(dst_base + (size_t)ci * CHUNK32
                  + (uint32_t)((((ks * 2 + limb) * 4 + wr) * 32 + t) * 16)) = pk;
    }
}

// ---------------------------------------------------------------------------
__device__ __forceinline__ void mma16816(float* c, uint4 a,
                                         uint32_t b0, uint32_t b1) {
    asm volatile(
        "mma.sync.aligned.m16n8k16.row.col.f32.bf16.bf16.f32 "
        "{%0,%1,%2,%3}, {%4,%5,%6,%7}, {%8,%9}, {%0,%1,%2,%3};"
        : "+f"(c[0]), "+f"(c[1]), "+f"(c[2]), "+f"(c[3])
        : "r"(a.x), "r"(a.y), "r"(a.z), "r"(a.w), "r"(b0), "r"(b1));
}

// One 16KB A sub-chunk (4 k16-steps), n8 slice per warp (12 HMMA).
__device__ __forceinline__ void mma_sub_n8(
    const unsigned char* sa, const unsigned char* sw, int ksb,
    int wr, int nhs, int nfl, int lid, float a0[4], float a1[4]) {
    #pragma unroll
    for (int kl = 0; kl < 4; ++kl) {
        uint4 ahi = *(const uint4*)(sa +
            (uint32_t)((((kl * 2 + 0) * 4 + wr) * 32 + lid) * 16));
        uint4 alo = *(const uint4*)(sa +
            (uint32_t)((((kl * 2 + 1) * 4 + wr) * 32 + lid) * 16));
        int ksg = ksb + kl;
        uint2 bhi = *(const uint2*)(sw +
            (uint32_t)((((ksg * 2 + 0) * 2 + nhs) * 32 + lid) * 16 + nfl * 8));
        uint2 blo = *(const uint2*)(sw +
            (uint32_t)((((ksg * 2 + 1) * 2 + nhs) * 32 + lid) * 16 + nfl * 8));
        mma16816(a0, ahi, bhi.x, bhi.y);
        mma16816(a1, ahi, blo.x, blo.y);
        mma16816(a1, alo, bhi.x, bhi.y);
    }
}

__device__ __forceinline__ float sigf(float x) {
    return 1.0f / (1.0f + __expf(-x));
}
__device__ __forceinline__ void bar_arrive(unsigned* p) {
    asm volatile("red.release.gpu.global.add.u32 [%0], 1;" :: "l"(p) : "memory");
}
__device__ __forceinline__ void bar_wait(const unsigned* p, unsigned target) {
    unsigned v;
    do {
        asm volatile("ld.acquire.gpu.global.u32 %0, [%1];"
                     : "=r"(v) : "l"(p) : "memory");
    } while (v < target);
}

// Build W fragments (32 ks, 2 limbs, 2 nh halves) from a 512-k window.
__device__ __forceinline__ void build_wfrags(
    unsigned char* sw, const float* w, int ubase, int tid, int nthreads) {
    for (int sl = tid; sl < 4096; sl += nthreads) {
        int t    = sl & 31;
        int nhs  = (sl >> 5) & 1;
        int limb = (sl >> 6) & 1;
        int ks   = sl >> 7;               // 0..31
        uint4 pk;
        unsigned* pq = (unsigned*)&pk;
        #pragma unroll
        for (int q = 0; q < 4; ++q) {
            int nf  = 2 * nhs + (q >> 1);
            int k   = ks * 16 + (t & 3) * 2 + (q & 1) * 8;   // 0..511
            int col = nf * 8 + (t >> 2);
            int gcol = ((col >> 3) << 9) + ubase + (col & 7);
            float v0 = w[(size_t)k * 2048 + gcol];
            float v1 = w[(size_t)(k + 1) * 2048 + gcol];
            unsigned short u0 = limb ? bf16lo(v0) : bf16hi(v0);
            unsigned short u1 = limb ? bf16lo(v1) : bf16hi(v1);
            pq[q] = (unsigned)u0 | ((unsigned)u1 << 16);
        }
        *(uint4*)(sw + (uint32_t)((((ks * 2 + limb) * 2 + nhs) * 32 + t) * 16)) = pk;
    }
}

// ---------------------------------------------------------------------------
// bulk x-GEMM: zx[dir][blk][s][b][32] = x @ Wx   (1024 blocks, no barriers)
// ---------------------------------------------------------------------------
extern __shared__ __align__(16) unsigned char smraw[];

__global__ void __launch_bounds__(THREADS, 1)
birnn_xgemm_kernel(const float* __restrict__ kern_f,
                   const float* __restrict__ kern_b) {
    const int tid = threadIdx.x;
    const int wid = tid >> 5, lid = tid & 31;
    const int wr = wid & 3, nf = wid >> 2;    // nf 0..3 (n8 slice)
    const int nhs = nf >> 1, nfl = nf & 1;
    const int bx = blockIdx.x;
    const int dir = bx >> 9;
    const int blk = (bx >> 3) & 63;
    const int s0  = (bx & 7) * 128;
    const int ubase = blk * 8;

    build_wfrags(smraw + XG_W, dir ? kern_b : kern_f, ubase, tid, THREADS);
    __syncthreads();

    uint32_t smem_u32 = (uint32_t)__cvta_generic_to_shared(smraw);

    auto stage = [&](int it) {
        const unsigned char* src = g_xA
            + (size_t)(s0 + (it >> 3)) * XSTEP_B + (uint32_t)(it & 7) * SUB_B;
        uint32_t dst = smem_u32 + XG_A + (uint32_t)(it & 3) * SUB_B;
        #pragma unroll
        for (int j = 0; j < 2; ++j) {     // 1024 x 16B / 512 threads
            uint32_t off = (uint32_t)(j * 512 + tid) * 16;
            asm volatile("cp.async.cg.shared.global [%0], [%1], 16;\n"
                         :: "r"(dst + off), "l"(src + off));
        }
        asm volatile("cp.async.commit_group;\n");
    };

    stage(0); stage(1); stage(2);

    float a0[4], a1[4];
    #pragma unroll 1
    for (int it = 0; it < 1024; ++it) {
        const int c = it & 7;
        if (c == 0) {
            #pragma unroll
            for (int i = 0; i < 4; ++i) { a0[i] = 0.0f; a1[i] = 0.0f; }
        }
        asm volatile("cp.async.wait_group 2;\n" ::: "memory");
        __syncthreads();
        if (it + 3 < 1024) stage(it + 3);
        else asm volatile("cp.async.commit_group;\n");
        mma_sub_n8(smraw + XG_A + (uint32_t)(it & 3) * SUB_B, smraw + XG_W,
                   c * 4, wr, nhs, nfl, lid, a0, a1);
        if (c == 7) {
            const int sidx = s0 + (it >> 3);
            float* dst = &g_zx[dir][blk][sidx][0];
            int row = wr * 16 + (lid >> 2);
            int col = nf * 8 + (lid & 3) * 2;
            *(float2*)&dst[row * 32 + col]       = make_float2(a0[0] + a1[0],
                                                               a0[1] + a1[1]);
            *(float2*)&dst[(row + 8) * 32 + col] = make_float2(a0[2] + a1[2],
                                                               a0[3] + a1[3]);
        }
    }
}

// ---------------------------------------------------------------------------
// recurrent loop: 128 persistent blocks (64/dir), h-half GEMM only.
// ---------------------------------------------------------------------------
__global__ void __launch_bounds__(THREADS, 1)
birnn_loop_kernel(const float* __restrict__ rkern_f,
                  const float* __restrict__ bias_f,
                  const float* __restrict__ rkern_b,
                  const float* __restrict__ bias_b,
                  float* __restrict__ out) {
    const int tid = threadIdx.x;
    const int wid = tid >> 5, lid = tid & 31;
    const int wr = wid & 3, nf = wid >> 2;
    const int nhs = nf >> 1, nfl = nf & 1;
    const int dir = blockIdx.x >> 6;
    const int blk = blockIdx.x & 63;
    const int ubase = blk * 8;

    const float* rkern = dir ? rkern_b : rkern_f;
    const float* bias  = dir ? bias_b  : bias_f;

    uint32_t smem_u32 = (uint32_t)__cvta_generic_to_shared(smraw);
    float* zxS   = (float*)(smraw + LP_ZX);   // [64][40]
    float* zS    = (float*)(smraw + LP_Z);    // [64][34]
    float* sH    = (float*)(smraw + LP_H);    // [64][9]
    float* sC    = (float*)(smraw + LP_C);    // [64][9]
    float* biasS = (float*)(smraw + LP_BI);   // [32]
    int*   sLen  = (int*)(smraw + LP_LEN);

    build_wfrags(smraw + LP_W, rkern, ubase, tid, THREADS);
    if (tid < 32) {
        int gcol = ((tid >> 3) << 9) + ubase + (tid & 7);
        biasS[tid] = bias[gcol];
    }
    for (int i = tid; i < Bk * 9; i += THREADS) { sH[i] = 0.0f; sC[i] = 0.0f; }
    if (tid < Bk) sLen[tid] = g_len[tid];
    __syncthreads();

    auto stage_h = [&](int c, int rp) {
        const unsigned char* src = &g_hA[dir][rp][0] + (uint32_t)c * SUB_B;
        uint32_t dst = smem_u32 + LP_A + (uint32_t)(c & 3) * SUB_B;
        #pragma unroll
        for (int j = 0; j < 2; ++j) {
            uint32_t off = (uint32_t)(j * 512 + tid) * 16;
            asm volatile("cp.async.cg.shared.global [%0], [%1], 16;\n"
                         :: "r"(dst + off), "l"(src + off));
        }
        asm volatile("cp.async.commit_group;\n");
    };
    auto stage_zx = [&](int sidx) {
        const float* src = &g_zx[dir][blk][sidx][0];
        {
            int i = tid;                       // 512 x 16B
            int b = i >> 3, p = i & 7;
            uint32_t dst = smem_u32 + LP_ZX + (uint32_t)((b * 40 + p * 4) * 4);
            asm volatile("cp.async.cg.shared.global [%0], [%1], 16;\n"
                         :: "r"(dst), "l"(src + (b * 32 + p * 4)));
        }
        asm volatile("cp.async.commit_group;\n");
    };

    // prologue: zx for step 0
    stage_zx(dir ? (Sk - 1) : 0);

    float a0[4], a1[4];

    for (int t = 0; t < Sk; ++t) {
        const int rp = t & 1, wp = rp ^ 1;
        const int sidx = dir ? (Sk - 1 - t) : t;

        // wait for h(t-1) publication from all blocks of this direction
        if (tid == 0) bar_wait(&g_bar[dir][0], (unsigned)t * (unsigned)NBLK_DIR);
        __syncthreads();

        stage_h(0, rp); stage_h(1, rp); stage_h(2, rp);

        #pragma unroll
        for (int i = 0; i < 4; ++i) { a0[i] = 0.0f; a1[i] = 0.0f; }

        #pragma unroll 1
        for (int c = 0; c < 8; ++c) {
            asm volatile("cp.async.wait_group 2;\n" ::: "memory");
            __syncthreads();
            if (c < 5) stage_h(c + 3, rp);
            else asm volatile("cp.async.commit_group;\n");
            mma_sub_n8(smraw + LP_A + (uint32_t)(c & 3) * SUB_B, smraw + LP_W,
                       c * 4, wr, nhs, nfl, lid, a0, a1);
        }

        // ---- accumulators -> zS ----
        {
            int row = wr * 16 + (lid >> 2);
            int col = nf * 8 + (lid & 3) * 2;
            *(float2*)&zS[row * 34 + col] =
                make_float2(a0[0] + a1[0], a0[1] + a1[1]);
            *(float2*)&zS[(row + 8) * 34 + col] =
                make_float2(a0[2] + a1[2], a0[3] + a1[3]);
        }
        asm volatile("cp.async.wait_group 0;\n" ::: "memory");   // zx tile
        __syncthreads();

        // ---- gates, mask, state update (512 tasks, 1 per thread) ----
        {
            int ul = tid & 7, b = tid >> 3;
            float zi = zS[b * 34 + ul]      + zxS[b * 40 + ul]      + biasS[ul];
            float zf = zS[b * 34 + 8 + ul]  + zxS[b * 40 + 8 + ul]  + biasS[8 + ul];
            float zg = zS[b * 34 + 16 + ul] + zxS[b * 40 + 16 + ul] + biasS[16 + ul];
            float zo = zS[b * 34 + 24 + ul] + zxS[b * 40 + 24 + ul] + biasS[24 + ul];
            float cold = sC[b * 9 + ul];
            float cn = sigf(zf) * cold + sigf(zi) * tanhf(zg);
            float hn = sigf(zo) * tanhf(cn);
            bool act = sidx < sLen[b];
            sC[b * 9 + ul] = act ? cn : cold;
            sH[b * 9 + ul] = act ? hn : sH[b * 9 + ul];
        }
        __syncthreads();

        // ---- publish h limbs into fragment layout (flat ks = blk>>1) ----
        {
            unsigned char* hbw = &g_hA[dir][wp][0];
            const int ks_h = blk >> 1;
            int p = tid & 3, limb = (tid >> 2) & 1, b = tid >> 3;
            float v0 = sH[b * 9 + 2 * p];
            float v1 = sH[b * 9 + 2 * p + 1];
            unsigned short u0 = limb ? bf16lo(v0) : bf16hi(v0);
            unsigned short u1 = limb ? bf16lo(v1) : bf16hi(v1);
            unsigned val = (unsigned)u0 | ((unsigned)u1 << 16);
            int tslot = (b & 7) * 4 + p;
            int j = ((b >> 3) & 1) + 2 * (blk & 1);
            unsigned* dst = (unsigned*)(hbw +
                (uint32_t)((((ks_h * 2 + limb) * 4 + (b >> 4)) * 32 + tslot) * 16
                           + j * 4));
            __stcg(dst, val);
        }
        __syncthreads();

        // arrive (release publishes the stcg writes above)
        if (tid == 0) bar_arrive(&g_bar[dir][0]);

        // ---- off critical path: out stores + zx prefetch for t+1 ----
        {
            int ul = tid & 7, b = tid >> 3;
            out[((size_t)b * Sk + sidx) * (2 * Uk) + dir * Uk + ubase + ul]
                = sH[b * 9 + ul];
        }
        if (t + 1 < Sk) stage_zx(dir ? (Sk - 2 - t) : (t + 1));
    }

    // ---- final states: h_f, c_f, h_b, c_b ----
    {
        const size_t obase = (size_t)Bk * Sk * (2 * Uk);
        int ul = tid & 7, b = tid >> 3;
        int ug = ubase + ul;
        size_t doff = obase + (size_t)dir * 2 * Bk * Uk;
        out[doff + (size_t)b * Uk + ug] = sH[b * 9 + ul];
        out[doff + (size_t)Bk * Uk + (size_t)b * Uk + ug] = sC[b * 9 + ul];
    }
}

// ---------------------------------------------------------------------------
extern "C" void kernel_launch(void* const* d_in, const int* in_sizes, int n_in,
                              void* d_out, int out_size) {
    const float* x    = (const float*)d_in[0];
    const void*  mask = d_in[1];
    const float* kf   = (const float*)d_in[2];
    const float* rkf  = (const float*)d_in[3];
    const float* bf   = (const float*)d_in[4];
    const float* kb   = (const float*)d_in[5];
    const float* rkb  = (const float*)d_in[6];
    const float* bb   = (const float*)d_in[7];
    float* out = (float*)d_out;

    cudaFuncSetAttribute(birnn_xgemm_kernel,
                         cudaFuncAttributeMaxDynamicSharedMemorySize, XG_SMEM);
    cudaFuncSetAttribute(birnn_loop_kernel,
                         cudaFuncAttributeMaxDynamicSharedMemorySize, LP_SMEM);

    birnn_init_kernel<<<64, 256>>>(mask);
    birnn_xconv_kernel<<<Sk, 256>>>(x);
    birnn_xgemm_kernel<<<1024, THREADS, XG_SMEM>>>(kf, kb);
    birnn_loop_kernel<<<2 * NBLK_DIR, THREADS, LP_SMEM>>>(
        rkf, bf, rkb, bb, out);
}

// round 17
// speedup vs baseline: 1.7003x; 1.4269x over previous
#include <cuda_runtime.h>
#include <cuda_bf16.h>
#include <cstdint>

// ---------------------------------------------------------------------------
// BiRNN (bidirectional masked LSTM), B=64, S=1024, D=U=512.
// Split design (R13 structure, 256-thread blocks):
//   1) birnn_xconv : x -> bf16 limb fragments (mma register layout) in g_xA
//   2) birnn_xgemm : zx = x @ Wx for ALL timesteps (bulk GEMM, 1024 blocks)
//   3) birnn_loop  : sequential recurrence, h-half GEMM only (K=512),
//                    128 persistent blocks (64/dir), per-dir grid barrier.
//      This round: 8-deep staging ring filled up-front each step (4 paired
//      wait checkpoints), fused gates+publish epilogue, exp-based tanh.
// mma.sync m16n8k16 bf16 with limb-split (3 products) -> fp32-grade accuracy.
// ---------------------------------------------------------------------------

namespace {
constexpr int Bk = 64;
constexpr int Sk = 1024;
constexpr int Dk = 512;
constexpr int Uk = 512;
constexpr int THREADS  = 256;          // 8 warps: wr = wid&3 (M16), nh = wid>>2 (N16)
constexpr int NBLK_DIR = 64;
constexpr uint32_t SUB_B   = 16384;    // 16KB sub-chunk = 4 k16-steps
constexpr uint32_t CHUNK32 = 32768;    // xconv 32KB chunk granularity
constexpr uint32_t XSTEP_B = 131072;   // x fragments per timestep (32 ks)

// xgemm smem layout (bytes)
constexpr uint32_t XG_W    = 0;        // W-x frags: 32ks x2limb x2nh x32 x16B = 64KB
constexpr uint32_t XG_A    = 65536;    // ring: 4 x 16KB
constexpr uint32_t XG_SMEM = 131072;

// loop smem layout (bytes) — 8-deep A ring
constexpr uint32_t LP_W    = 0;        // W-h frags: 64KB
constexpr uint32_t LP_A    = 65536;    // ring: 8 x 16KB = 128KB
constexpr uint32_t LP_ZX   = 196608;   // zx tile [64][40] f32 = 10240
constexpr uint32_t LP_Z    = 206848;   // zS [64][34] f32 = 8704
constexpr uint32_t LP_H    = 215552;   // sH [64][9] f32 = 2304
constexpr uint32_t LP_C    = 217856;   // sC [64][9] f32 = 2304
constexpr uint32_t LP_BI   = 220160;   // bias [32] f32
constexpr uint32_t LP_LEN  = 220288;   // lengths [64] int
constexpr uint32_t LP_SMEM = 220544;   // < 227KB
}

// persistent device state
__device__ __align__(16) unsigned char g_xA[(size_t)Sk * XSTEP_B];   // 128 MB
__device__ __align__(16) unsigned char g_hA[2][2][XSTEP_B];          // 512 KB
__device__ float    g_zx[2][NBLK_DIR][Sk][Bk * 32];                  // 1 GB
__device__ int      g_len[Bk];
__device__ unsigned g_bar[2][32];      // per-dir counters, 128B apart

// ---------------------------------------------------------------------------
// init (grid 64): zero h buffers + barriers, recover lengths[] in parallel.
// ---------------------------------------------------------------------------
__global__ void birnn_init_kernel(const void* __restrict__ maskraw) {
    const int b = blockIdx.x;       // 64 blocks, 256 threads
    const int tid = threadIdx.x;
    uint4* hz = (uint4*)&g_hA[0][0][0];
    hz[b * 512 + tid]       = make_uint4(0, 0, 0, 0);
    hz[b * 512 + 256 + tid] = make_uint4(0, 0, 0, 0);
    if (b == 0 && tid < 2) g_bar[tid][0] = 0u;

    __shared__ int s_cnt8, s_bad8, s_cnt32;
    if (tid == 0) { s_cnt8 = 0; s_bad8 = 0; s_cnt32 = 0; }
    __syncthreads();
    if (tid < 64) {
        const uchar4* m = (const uchar4*)((const unsigned char*)maskraw + b * 1024);
        int c = 0, bad = 0;
        #pragma unroll
        for (int j = 0; j < 4; ++j) {
            uchar4 v = m[tid * 4 + j];
            c   += (v.x != 0) + (v.y != 0) + (v.z != 0) + (v.w != 0);
            bad += (v.x > 1)  + (v.y > 1)  + (v.z > 1)  + (v.w > 1);
        }
        atomicAdd(&s_cnt8, c);
        if (bad) atomicAdd(&s_bad8, 1);
    }
    {
        const uint4* m = (const uint4*)((const unsigned*)maskraw + b * 1024);
        uint4 v = m[tid];
        int c = (v.x != 0u) + (v.y != 0u) + (v.z != 0u) + (v.w != 0u);
        atomicAdd(&s_cnt32, c);
    }
    __syncthreads();
    if (tid == 0) {
        const unsigned char* m8 = (const unsigned char*)maskraw + b * 1024;
        int cnt8 = s_cnt8;
        bool ok8 = (s_bad8 == 0) && (cnt8 >= Sk / 2);
        if (ok8) {
            if (m8[cnt8 - 1] == 0) ok8 = false;
            else if (cnt8 < Sk && m8[cnt8] != 0) ok8 = false;
        }
        g_len[b] = ok8 ? cnt8 : s_cnt32;
    }
}

// ---------------------------------------------------------------------------
// bf16 limb helpers
// ---------------------------------------------------------------------------
__device__ __forceinline__ unsigned short bf16hi(float v) {
    __nv_bfloat16 h = __float2bfloat16(v);
    return *(unsigned short*)&h;
}
__device__ __forceinline__ unsigned short bf16lo(float v) {
    __nv_bfloat16 h = __float2bfloat16(v);
    float r = v - __bfloat162float(h);
    __nv_bfloat16 l = __float2bfloat16(r);
    return *(unsigned short*)&l;
}

// ---------------------------------------------------------------------------
// x pre-conversion: fp32 -> bf16 limb fragments in mma register layout.
// ---------------------------------------------------------------------------
__global__ void birnn_xconv_kernel(const float* __restrict__ x) {
    const int s = blockIdx.x;
    const int tid = threadIdx.x;   // 256
    unsigned char* dst_base = g_xA + (size_t)s * XSTEP_B;
    for (int sl = tid; sl < 8192; sl += 256) {
        int t    = sl & 31;
        int wr   = (sl >> 5) & 3;
        int limb = (sl >> 7) & 1;
        int ks   = (sl >> 8) & 7;
        int ci   = sl >> 11;
        uint4 pk;
        unsigned* pq = (unsigned*)&pk;
        #pragma unroll
        for (int j = 0; j < 4; ++j) {
            int row = wr * 16 + (t >> 2) + 8 * (j & 1);
            int k   = (ci * 8 + ks) * 16 + (t & 3) * 2 + 8 * (j >> 1);
            float2 v = *(const float2*)&x[((size_t)row * Sk + s) * Dk + k];
            unsigned short u0 = limb ? bf16lo(v.x) : bf16hi(v.x);
            unsigned short u1 = limb ? bf16lo(v.y) : bf16hi(v.y);
            pq[j] = (unsigned)u0 | ((unsigned)u1 << 16);
        }
        *(uint4*)(dst_base + (size_t)ci * CHUNK32
                  + (uint32_t)((((ks * 2 + limb) * 4 + wr) * 32 + t) * 16)) = pk;
    }
}

// ---------------------------------------------------------------------------
__device__ __forceinline__ void mma16816(float* c, uint4 a,
                                         uint32_t b0, uint32_t b1) {
    asm volatile(
        "mma.sync.aligned.m16n8k16.row.col.f32.bf16.bf16.f32 "
        "{%0,%1,%2,%3}, {%4,%5,%6,%7}, {%8,%9}, {%0,%1,%2,%3};"
        : "+f"(c[0]), "+f"(c[1]), "+f"(c[2]), "+f"(c[3])
        : "r"(a.x), "r"(a.y), "r"(a.z), "r"(a.w), "r"(b0), "r"(b1));
}

// One 16KB A sub-chunk (4 k16-steps) from SMEM against resident W fragments.
__device__ __forceinline__ void mma_sub(
    const unsigned char* sa, const unsigned char* sw, int ksb,
    int wr, int nh, int lid, float a0[2][4], float a1[2][4]) {
    #pragma unroll
    for (int kl = 0; kl < 4; ++kl) {
        uint4 ahi = *(const uint4*)(sa +
            (uint32_t)((((kl * 2 + 0) * 4 + wr) * 32 + lid) * 16));
        uint4 alo = *(const uint4*)(sa +
            (uint32_t)((((kl * 2 + 1) * 4 + wr) * 32 + lid) * 16));
        int ksg = ksb + kl;
        uint4 bhi = *(const uint4*)(sw +
            (uint32_t)((((ksg * 2 + 0) * 2 + nh) * 32 + lid) * 16));
        uint4 blo = *(const uint4*)(sw +
            (uint32_t)((((ksg * 2 + 1) * 2 + nh) * 32 + lid) * 16));
        mma16816(a0[0], ahi, bhi.x, bhi.y);
        mma16816(a0[1], ahi, bhi.z, bhi.w);
        mma16816(a1[0], ahi, blo.x, blo.y);
        mma16816(a1[1], ahi, blo.z, blo.w);
        mma16816(a1[0], alo, bhi.x, bhi.y);
        mma16816(a1[1], alo, bhi.z, bhi.w);
    }
}

__device__ __forceinline__ float sigf(float x) {
    return 1.0f / (1.0f + __expf(-x));
}
// exp-based tanh: saturates correctly for |x| large (exp -> inf/0).
__device__ __forceinline__ float tanh_e(float x) {
    return 1.0f - 2.0f / (__expf(2.0f * x) + 1.0f);
}
__device__ __forceinline__ void bar_arrive(unsigned* p) {
    asm volatile("red.release.gpu.global.add.u32 [%0], 1;" :: "l"(p) : "memory");
}
__device__ __forceinline__ void bar_wait(const unsigned* p, unsigned target) {
    unsigned v;
    do {
        asm volatile("ld.acquire.gpu.global.u32 %0, [%1];"
                     : "=r"(v) : "l"(p) : "memory");
    } while (v < target);
}

// Build W fragments (32 ks, 2 limbs, 2 nh halves) from a 512-k window.
__device__ __forceinline__ void build_wfrags(
    unsigned char* sw, const float* w, int ubase, int tid) {
    for (int sl = tid; sl < 4096; sl += THREADS) {
        int t    = sl & 31;
        int nhs  = (sl >> 5) & 1;
        int limb = (sl >> 6) & 1;
        int ks   = sl >> 7;               // 0..31
        uint4 pk;
        unsigned* pq = (unsigned*)&pk;
        #pragma unroll
        for (int q = 0; q < 4; ++q) {
            int nf  = 2 * nhs + (q >> 1);
            int k   = ks * 16 + (t & 3) * 2 + (q & 1) * 8;   // 0..511
            int col = nf * 8 + (t >> 2);
            int gcol = ((col >> 3) << 9) + ubase + (col & 7);
            float v0 = w[(size_t)k * 2048 + gcol];
            float v1 = w[(size_t)(k + 1) * 2048 + gcol];
            unsigned short u0 = limb ? bf16lo(v0) : bf16hi(v0);
            unsigned short u1 = limb ? bf16lo(v1) : bf16hi(v1);
            pq[q] = (unsigned)u0 | ((unsigned)u1 << 16);
        }
        *(uint4*)(sw + (uint32_t)((((ks * 2 + limb) * 2 + nhs) * 32 + t) * 16)) = pk;
    }
}

// ---------------------------------------------------------------------------
// bulk x-GEMM: zx[dir][blk][s][b][32] = x @ Wx   (1024 blocks, no barriers)
// ---------------------------------------------------------------------------
extern __shared__ __align__(16) unsigned char smraw[];

__global__ void __launch_bounds__(THREADS, 1)
birnn_xgemm_kernel(const float* __restrict__ kern_f,
                   const float* __restrict__ kern_b) {
    const int tid = threadIdx.x;
    const int wid = tid >> 5, lid = tid & 31;
    const int wr = wid & 3, nh = wid >> 2;
    const int bx = blockIdx.x;
    const int dir = bx >> 9;
    const int blk = (bx >> 3) & 63;
    const int s0  = (bx & 7) * 128;
    const int ubase = blk * 8;

    build_wfrags(smraw + XG_W, dir ? kern_b : kern_f, ubase, tid);
    __syncthreads();

    uint32_t smem_u32 = (uint32_t)__cvta_generic_to_shared(smraw);

    auto stage = [&](int it) {
        const unsigned char* src = g_xA
            + (size_t)(s0 + (it >> 3)) * XSTEP_B + (uint32_t)(it & 7) * SUB_B;
        uint32_t dst = smem_u32 + XG_A + (uint32_t)(it & 3) * SUB_B;
        #pragma unroll
        for (int j = 0; j < 4; ++j) {     // 1024 x 16B / 256 threads
            uint32_t off = (uint32_t)(j * 256 + tid) * 16;
            asm volatile("cp.async.cg.shared.global [%0], [%1], 16;\n"
                         :: "r"(dst + off), "l"(src + off));
        }
        asm volatile("cp.async.commit_group;\n");
    };

    stage(0); stage(1); stage(2);

    float a0[2][4], a1[2][4];
    #pragma unroll 1
    for (int it = 0; it < 1024; ++it) {
        const int c = it & 7;
        if (c == 0) {
            #pragma unroll
            for (int f = 0; f < 2; ++f)
                #pragma unroll
                for (int i = 0; i < 4; ++i) { a0[f][i] = 0.0f; a1[f][i] = 0.0f; }
        }
        asm volatile("cp.async.wait_group 2;\n" ::: "memory");
        __syncthreads();
        if (it + 3 < 1024) stage(it + 3);
        else asm volatile("cp.async.commit_group;\n");
        mma_sub(smraw + XG_A + (uint32_t)(it & 3) * SUB_B, smraw + XG_W,
                c * 4, wr, nh, lid, a0, a1);
        if (c == 7) {
            const int sidx = s0 + (it >> 3);
            float* dst = &g_zx[dir][blk][sidx][0];
            #pragma unroll
            for (int f = 0; f < 2; ++f) {
                int row = wr * 16 + (lid >> 2);
                int col = (2 * nh + f) * 8 + (lid & 3) * 2;
                *(float2*)&dst[row * 32 + col] =
                    make_float2(a0[f][0] + a1[f][0], a0[f][1] + a1[f][1]);
                *(float2*)&dst[(row + 8) * 32 + col] =
                    make_float2(a0[f][2] + a1[f][2], a0[f][3] + a1[f][3]);
            }
        }
    }
}

// ---------------------------------------------------------------------------
// recurrent loop: 128 persistent blocks (64/dir), h-half GEMM only.
// ---------------------------------------------------------------------------
__global__ void __launch_bounds__(THREADS, 1)
birnn_loop_kernel(const float* __restrict__ rkern_f,
                  const float* __restrict__ bias_f,
                  const float* __restrict__ rkern_b,
                  const float* __restrict__ bias_b,
                  float* __restrict__ out) {
    const int tid = threadIdx.x;
    const int wid = tid >> 5, lid = tid & 31;
    const int wr = wid & 3, nh = wid >> 2;
    const int dir = blockIdx.x >> 6;
    const int blk = blockIdx.x & 63;
    const int ubase = blk * 8;

    const float* rkern = dir ? rkern_b : rkern_f;
    const float* bias  = dir ? bias_b  : bias_f;

    uint32_t smem_u32 = (uint32_t)__cvta_generic_to_shared(smraw);
    float* zxS   = (float*)(smraw + LP_ZX);   // [64][40]
    float* zS    = (float*)(smraw + LP_Z);    // [64][34]
    float* sH    = (float*)(smraw + LP_H);    // [64][9]
    float* sC    = (float*)(smraw + LP_C);    // [64][9]
    float* biasS = (float*)(smraw + LP_BI);   // [32]
    int*   sLen  = (int*)(smraw + LP_LEN);

    build_wfrags(smraw + LP_W, rkern, ubase, tid);
    if (tid < 32) {
        int gcol = ((tid >> 3) << 9) + ubase + (tid & 7);
        biasS[tid] = bias[gcol];
    }
    for (int i = tid; i < Bk * 9; i += THREADS) { sH[i] = 0.0f; sC[i] = 0.0f; }
    if (tid < Bk) sLen[tid] = g_len[tid];
    __syncthreads();

    auto stage_h = [&](int c, int rp) {
        const unsigned char* src = &g_hA[dir][rp][0] + (uint32_t)c * SUB_B;
        uint32_t dst = smem_u32 + LP_A + (uint32_t)c * SUB_B;   // 8-deep ring
        #pragma unroll
        for (int j = 0; j < 4; ++j) {
            uint32_t off = (uint32_t)(j * 256 + tid) * 16;
            asm volatile("cp.async.cg.shared.global [%0], [%1], 16;\n"
                         :: "r"(dst + off), "l"(src + off));
        }
        asm volatile("cp.async.commit_group;\n");
    };
    auto stage_zx = [&](int sidx) {
        const float* src = &g_zx[dir][blk][sidx][0];
        #pragma unroll
        for (int r = 0; r < 2; ++r) {
            int i = tid + r * THREADS;         // 512 x 16B
            int b = i >> 3, p = i & 7;
            uint32_t dst = smem_u32 + LP_ZX + (uint32_t)((b * 40 + p * 4) * 4);
            asm volatile("cp.async.cg.shared.global [%0], [%1], 16;\n"
                         :: "r"(dst), "l"(src + (b * 32 + p * 4)));
        }
        asm volatile("cp.async.commit_group;\n");
    };

    // prologue: zx for step 0
    stage_zx(dir ? (Sk - 1) : 0);

    float a0[2][4], a1[2][4];
    const int ks_h = blk >> 1;
    const int pb = tid >> 2, pp = tid & 3;   // fused-epilogue mapping

    for (int t = 0; t < Sk; ++t) {
        const int rp = t & 1, wp = rp ^ 1;
        const int sidx = dir ? (Sk - 1 - t) : t;

        // wait for h(t-1) publication from all blocks of this direction
        if (tid == 0) bar_wait(&g_bar[dir][0], (unsigned)t * (unsigned)NBLK_DIR);
        __syncthreads();

        // stage ALL 8 chunks up-front (max MLP; burst drains behind compute)
        #pragma unroll
        for (int c = 0; c < 8; ++c) stage_h(c, rp);

        #pragma unroll
        for (int f = 0; f < 2; ++f)
            #pragma unroll
            for (int i = 0; i < 4; ++i) { a0[f][i] = 0.0f; a1[f][i] = 0.0f; }

        // 4 paired checkpoints: before pair cp need chunks 2cp,2cp+1 landed
        #pragma unroll
        for (int cp = 0; cp < 4; ++cp) {
            if (cp == 0)      asm volatile("cp.async.wait_group 6;\n" ::: "memory");
            else if (cp == 1) asm volatile("cp.async.wait_group 4;\n" ::: "memory");
            else if (cp == 2) asm volatile("cp.async.wait_group 2;\n" ::: "memory");
            else              asm volatile("cp.async.wait_group 0;\n" ::: "memory");
            __syncthreads();
            mma_sub(smraw + LP_A + (uint32_t)(2 * cp) * SUB_B, smraw + LP_W,
                    (2 * cp) * 4, wr, nh, lid, a0, a1);
            mma_sub(smraw + LP_A + (uint32_t)(2 * cp + 1) * SUB_B, smraw + LP_W,
                    (2 * cp + 1) * 4, wr, nh, lid, a0, a1);
        }

        // ---- accumulators -> zS ----
        #pragma unroll
        for (int f = 0; f < 2; ++f) {
            int row = wr * 16 + (lid >> 2);
            int col = (2 * nh + f) * 8 + (lid & 3) * 2;
            *(float2*)&zS[row * 34 + col] =
                make_float2(a0[f][0] + a1[f][0], a0[f][1] + a1[f][1]);
            *(float2*)&zS[(row + 8) * 34 + col] =
                make_float2(a0[f][2] + a1[f][2], a0[f][3] + a1[f][3]);
        }
        __syncthreads();   // zS + (zx already landed via wait_group 0)

        // ---- fused gates + publish: thread owns (b=pb, units 2pp, 2pp+1) ----
        {
            float hv[2];
            const bool act = sidx < sLen[pb];
            #pragma unroll
            for (int e = 0; e < 2; ++e) {
                int ul = 2 * pp + e;
                float zi = zS[pb * 34 + ul]      + zxS[pb * 40 + ul]      + biasS[ul];
                float zf = zS[pb * 34 + 8 + ul]  + zxS[pb * 40 + 8 + ul]  + biasS[8 + ul];
                float zg = zS[pb * 34 + 16 + ul] + zxS[pb * 40 + 16 + ul] + biasS[16 + ul];
                float zo = zS[pb * 34 + 24 + ul] + zxS[pb * 40 + 24 + ul] + biasS[24 + ul];
                float cold = sC[pb * 9 + ul];
                float cn = sigf(zf) * cold + sigf(zi) * tanh_e(zg);
                float hn = sigf(zo) * tanh_e(cn);
                float co = act ? cn : cold;
                float ho = act ? hn : sH[pb * 9 + ul];
                sC[pb * 9 + ul] = co;
                sH[pb * 9 + ul] = ho;
                hv[e] = ho;
            }
            // publish both limb words directly from registers
            unsigned char* hbw = &g_hA[dir][wp][0];
            int tslot = (pb & 7) * 4 + pp;
            int j = ((pb >> 3) & 1) + 2 * (blk & 1);
            unsigned w0 = (unsigned)bf16hi(hv[0]) | ((unsigned)bf16hi(hv[1]) << 16);
            unsigned w1 = (unsigned)bf16lo(hv[0]) | ((unsigned)bf16lo(hv[1]) << 16);
            __stcg((unsigned*)(hbw +
                (uint32_t)((((ks_h * 2 + 0) * 4 + (pb >> 4)) * 32 + tslot) * 16
                           + j * 4)), w0);
            __stcg((unsigned*)(hbw +
                (uint32_t)((((ks_h * 2 + 1) * 4 + (pb >> 4)) * 32 + tslot) * 16
                           + j * 4)), w1);
        }
        __syncthreads();

        // arrive (release publishes the stcg writes above)
        if (tid == 0) bar_arrive(&g_bar[dir][0]);

        // ---- off critical path: out stores + zx prefetch for t+1 ----
        #pragma unroll
        for (int r = 0; r < 2; ++r) {
            int id = tid + r * THREADS;
            int ul = id & 7, b = id >> 3;
            out[((size_t)b * Sk + sidx) * (2 * Uk) + dir * Uk + ubase + ul]
                = sH[b * 9 + ul];
        }
        if (t + 1 < Sk) stage_zx(dir ? (Sk - 2 - t) : (t + 1));
    }

    // ---- final states: h_f, c_f, h_b, c_b ----
    const size_t obase = (size_t)Bk * Sk * (2 * Uk);
    #pragma unroll
    for (int r = 0; r < 2; ++r) {
        int id = tid + r * THREADS;
        int ul = id & 7, b = id >> 3;
        int ug = ubase + ul;
        size_t doff = obase + (size_t)dir * 2 * Bk * Uk;
        out[doff + (size_t)b * Uk + ug] = sH[b * 9 + ul];
        out[doff + (size_t)Bk * Uk + (size_t)b * Uk + ug] = sC[b * 9 + ul];
    }
}

// ---------------------------------------------------------------------------
extern "C" void kernel_launch(void* const* d_in, const int* in_sizes, int n_in,
                              void* d_out, int out_size) {
    const float* x    = (const float*)d_in[0];
    const void*  mask = d_in[1];
    const float* kf   = (const float*)d_in[2];
    const float* rkf  = (const float*)d_in[3];
    const float* bf   = (const float*)d_in[4];
    const float* kb   = (const float*)d_in[5];
    const float* rkb  = (const float*)d_in[6];
    const float* bb   = (const float*)d_in[7];
    float* out = (float*)d_out;

    cudaFuncSetAttribute(birnn_xgemm_kernel,
                         cudaFuncAttributeMaxDynamicSharedMemorySize, XG_SMEM);
    cudaFuncSetAttribute(birnn_loop_kernel,
                         cudaFuncAttributeMaxDynamicSharedMemorySize, LP_SMEM);

    birnn_init_kernel<<<64, 256>>>(mask);
    birnn_xconv_kernel<<<Sk, 256>>>(x);
    birnn_xgemm_kernel<<<1024, THREADS, XG_SMEM>>>(kf, kb);
    birnn_loop_kernel<<<2 * NBLK_DIR, THREADS, LP_SMEM>>>(
        rkf, bf, rkb, bb, out);
}